// round 17
// baseline (speedup 1.0000x reference)
#include <cuda_runtime.h>
#include <cuda_fp16.h>
#include <cuda_bf16.h>
#include <cstdint>

// Problem dims: msa [1,128,256,256] f32; left_w/right_w [256,32]; out_w [1024,128]
// out [1,256,256,128] f32.
#define S_DIM 128
#define R_DIM 256
#define M_DIM 256
#define C_DIM 32
#define CZ_DIM 128
#define RC_DIM 8192          // R*C
#define CE_DIM 1024          // C*C
#define RT_DIM 65536         // R*R

// ------------------------- device scratch (no allocs allowed) -------------------------
__device__ __half gA[RC_DIM * S_DIM];                 // left  [rc][s] fp16
__device__ __half gB[RC_DIM * S_DIM];                 // right [te][s] fp16
__device__ __half gP[(size_t)RT_DIM * CE_DIM];        // P [rt][ce] fp16
__device__ __half gWt[CZ_DIM * CE_DIM];               // W^T [z][ce] fp16 (gemm2)
__device__ unsigned short gWph[64 * M_DIM];           // proj weights hi [n][m] bf16
__device__ unsigned short gWpl[64 * M_DIM];           // proj weights lo [n][m] bf16

// ------------------------- helpers -------------------------
__device__ __forceinline__ unsigned lds2(const unsigned short* p) {
    return *reinterpret_cast<const unsigned*>(p);
}

__device__ __forceinline__ void mma16816h(float* c, const unsigned* a, const unsigned* b) {
    asm volatile(
        "mma.sync.aligned.m16n8k16.row.col.f32.f16.f16.f32 "
        "{%0,%1,%2,%3}, {%4,%5,%6,%7}, {%8,%9}, {%0,%1,%2,%3};\n"
        : "+f"(c[0]), "+f"(c[1]), "+f"(c[2]), "+f"(c[3])
        : "r"(a[0]), "r"(a[1]), "r"(a[2]), "r"(a[3]), "r"(b[0]), "r"(b[1]));
}

__device__ __forceinline__ void mma16816bf(float* c, const unsigned* a, const unsigned* b) {
    asm volatile(
        "mma.sync.aligned.m16n8k16.row.col.f32.bf16.bf16.f32 "
        "{%0,%1,%2,%3}, {%4,%5,%6,%7}, {%8,%9}, {%0,%1,%2,%3};\n"
        : "+f"(c[0]), "+f"(c[1]), "+f"(c[2]), "+f"(c[3])
        : "r"(a[0]), "r"(a[1]), "r"(a[2]), "r"(a[3]), "r"(b[0]), "r"(b[1]));
}

// .cg: bypass L1 allocation — tile data is consumed from smem, never re-read via L1.
__device__ __forceinline__ void cp16(void* smem, const void* g) {
    unsigned s = (unsigned)__cvta_generic_to_shared(smem);
    asm volatile("cp.async.cg.shared.global [%0], [%1], 16;\n" :: "r"(s), "l"(g));
}
#define CP_COMMIT() asm volatile("cp.async.commit_group;\n" ::: "memory")
#define CP_WAIT0()  asm volatile("cp.async.wait_group 0;\n" ::: "memory")
#define CP_WAIT1()  asm volatile("cp.async.wait_group 1;\n" ::: "memory")
#define CP_WAIT2()  asm volatile("cp.async.wait_group 2;\n" ::: "memory")
#define CP_WAIT3()  asm volatile("cp.async.wait_group 3;\n" ::: "memory")

__device__ __forceinline__ void bf_split(float x, unsigned short& h, unsigned short& l) {
    __nv_bfloat16 hb = __float2bfloat16_rn(x);
    h = *reinterpret_cast<unsigned short*>(&hb);
    __nv_bfloat16 lb = __float2bfloat16_rn(x - __bfloat162float(hb));
    l = *reinterpret_cast<unsigned short*>(&lb);
}

// ------------------------- kernel 0: weight prep -------------------------
__global__ __launch_bounds__(256) void prep_kernel(const float* __restrict__ lw,
                                                   const float* __restrict__ rw,
                                                   const float* __restrict__ ow) {
    int idx = blockIdx.x * 256 + threadIdx.x;
    if (idx < 64 * M_DIM) {
        int n = idx >> 8, m = idx & 255;
        float x = (n < 32) ? lw[m * 32 + n] : rw[m * 32 + (n - 32)];
        unsigned short h, l;
        bf_split(x, h, l);
        gWph[n * M_DIM + m] = h;
        gWpl[n * M_DIM + m] = l;
    }
    if (idx < CE_DIM * CZ_DIM) {     // idx = ce*128 + z
        int z = idx & 127, ce = idx >> 7;
        gWt[(size_t)z * CE_DIM + ce] = __float2half_rn(ow[idx]);
    }
}

// ------------------------- kernel 1: projection (tensor cores) -------------------------
#define PWS 264          // 256 + 8 pad
#define P_SWH 0
#define P_SWL (64 * PWS)
#define P_SAH (2 * 64 * PWS)
#define P_SAL (P_SAH + 128 * PWS)
#define PROJ_SMEM ((P_SAL + 128 * PWS) * 2)   // 202752 B
__global__ __launch_bounds__(256) void proj_tc_kernel(const float* __restrict__ msa) {
    extern __shared__ unsigned short sm16[];
    unsigned short* sWh = sm16 + P_SWH;
    unsigned short* sWl = sm16 + P_SWL;
    unsigned short* sAh = sm16 + P_SAH;
    unsigned short* sAl = sm16 + P_SAL;
    unsigned short* sT  = sm16 + P_SAH;

    const int tid = threadIdx.x;
    const int r = blockIdx.x;

#pragma unroll
    for (int i = 0; i < 16; ++i) {
        int idx = tid + 256 * i;
        int plane = idx >> 11, rem = idx & 2047;
        int n = rem >> 5, seg = rem & 31;
        unsigned short* dst = (plane ? sWl : sWh) + n * PWS + seg * 8;
        const unsigned short* src = (plane ? gWpl : gWph) + n * M_DIM + seg * 8;
        cp16(dst, src);
    }
    CP_COMMIT();

#pragma unroll
    for (int i = 0; i < 32; ++i) {
        int v = tid + 256 * i;
        int row = v >> 6, col4 = v & 63;
        const float4 x = *(const float4*)(msa + (((size_t)(row * R_DIM + r)) << 8) + col4 * 4);
        unsigned short h0, h1, h2, h3, l0, l1, l2, l3;
        bf_split(x.x, h0, l0); bf_split(x.y, h1, l1);
        bf_split(x.z, h2, l2); bf_split(x.w, h3, l3);
        int ofs = row * PWS + col4 * 4;
        *(unsigned*)(sAh + ofs)     = (unsigned)h0 | ((unsigned)h1 << 16);
        *(unsigned*)(sAh + ofs + 2) = (unsigned)h2 | ((unsigned)h3 << 16);
        *(unsigned*)(sAl + ofs)     = (unsigned)l0 | ((unsigned)l1 << 16);
        *(unsigned*)(sAl + ofs + 2) = (unsigned)l2 | ((unsigned)l3 << 16);
    }
    CP_WAIT0();
    __syncthreads();

    const int wid = tid >> 5, lane = tid & 31;
    const int g = lane >> 2, tg2 = (lane & 3) * 2;
    const int wm0 = (wid & 3) * 32, wn0 = (wid >> 2) * 32;

    float acc[2][4][4];
#pragma unroll
    for (int mi = 0; mi < 2; ++mi)
#pragma unroll
        for (int nj = 0; nj < 4; ++nj)
#pragma unroll
            for (int k = 0; k < 4; ++k) acc[mi][nj][k] = 0.f;

#pragma unroll
    for (int ks = 0; ks < 256; ks += 16) {
        unsigned ah[2][4], al[2][4], bh[4][2], bl[4][2];
#pragma unroll
        for (int mi = 0; mi < 2; ++mi) {
            int base = (wm0 + mi * 16 + g) * PWS + ks + tg2;
            ah[mi][0] = lds2(sAh + base);
            ah[mi][1] = lds2(sAh + base + 8 * PWS);
            ah[mi][2] = lds2(sAh + base + 8);
            ah[mi][3] = lds2(sAh + base + 8 * PWS + 8);
            al[mi][0] = lds2(sAl + base);
            al[mi][1] = lds2(sAl + base + 8 * PWS);
            al[mi][2] = lds2(sAl + base + 8);
            al[mi][3] = lds2(sAl + base + 8 * PWS + 8);
        }
#pragma unroll
        for (int nj = 0; nj < 4; ++nj) {
            int base = (wn0 + nj * 8 + g) * PWS + ks + tg2;
            bh[nj][0] = lds2(sWh + base);
            bh[nj][1] = lds2(sWh + base + 8);
            bl[nj][0] = lds2(sWl + base);
            bl[nj][1] = lds2(sWl + base + 8);
        }
#pragma unroll
        for (int mi = 0; mi < 2; ++mi)
#pragma unroll
            for (int nj = 0; nj < 4; ++nj) {
                mma16816bf(acc[mi][nj], ah[mi], bh[nj]);
                mma16816bf(acc[mi][nj], ah[mi], bl[nj]);
                mma16816bf(acc[mi][nj], al[mi], bh[nj]);
            }
    }
    __syncthreads();

#pragma unroll
    for (int mi = 0; mi < 2; ++mi)
#pragma unroll
        for (int nj = 0; nj < 4; ++nj)
#pragma unroll
            for (int half = 0; half < 2; ++half)
#pragma unroll
                for (int q = 0; q < 2; ++q) {
                    int n = wn0 + nj * 8 + tg2 + q;
                    int s = wm0 + mi * 16 + g + half * 8;
                    __half v = __float2half_rn(acc[mi][nj][half * 2 + q]);
                    sT[n * 136 + s] = *reinterpret_cast<unsigned short*>(&v);
                }
    __syncthreads();

#pragma unroll
    for (int i = 0; i < 4; ++i) {
        int v = tid + 256 * i;
        int col = v >> 4, seg = v & 15;
        uint4 d = *(uint4*)(sT + col * 136 + seg * 8);
        __half* dst = (col < 32)
            ? (__half*)gA + (((size_t)r * 32 + col) * S_DIM) + seg * 8
            : (__half*)gB + (((size_t)r * 32 + col - 32) * S_DIM) + seg * 8;
        *(uint4*)dst = d;
    }
}

// ------------------------- GEMM tiling (shared by gemm1/gemm2) -------------------------
// Block 64(M) x 128(N), warp 32x32, 8 warps. K-chunks of 32, 4-stage smem ring.
// Stage stride 40 ushorts (80B rows): fragment-load banks (20g+tq) mod 32 cover all
// 32 banks exactly once -> conflict-free.
#define GS 40
#define ST_A (64 * GS)                    // 2560 ush
#define ST_TOT (ST_A + 128 * GS)          // 7680 ush = 15360 B per stage
#define G_SMEM (4 * ST_TOT * 2)           // 61440 B
#define PE_STRIDE 1032

// ------------------------- kernel 2: GEMM1 -------------------------
// P[(r,c),(t,e)] = sum_s A[rc][s] * B[te][s].  K=128 = 4 chunks, ALL prefetched at
// CTA start (no buffer reuse -> no mid-loop fill stalls). 3 CTAs/SM.
__global__ __launch_bounds__(256, 3) void gemm1_kernel() {
    extern __shared__ unsigned short sm16[];
    unsigned short* sE = sm16;            // epilogue overlay (stages 0-1 region)

    const int tid = threadIdx.x;
    const int mb = blockIdx.y * 64, nb = blockIdx.x * 128;

    auto issue = [&](int st, int kc) {
        unsigned short* sA = sm16 + st * ST_TOT;
        unsigned short* sB = sA + ST_A;
        {   // A: 64 rows x 4 segs of 16B -> exactly 1 vec/thread
            int row = tid >> 2, seg = tid & 3;
            cp16(sA + row * GS + seg * 8,
                 (const __half*)gA + (size_t)(mb + row) * S_DIM + kc + seg * 8);
        }
#pragma unroll
        for (int i = 0; i < 2; ++i) {     // B: 128 rows x 4 segs
            int idx = tid + 256 * i;
            int row = idx >> 2, seg = idx & 3;
            cp16(sB + row * GS + seg * 8,
                 (const __half*)gB + (size_t)(nb + row) * S_DIM + kc + seg * 8);
        }
        CP_COMMIT();
    };

    issue(0, 0); issue(1, 32); issue(2, 64); issue(3, 96);

    const int wid = tid >> 5, lane = tid & 31;
    const int wm0 = (wid & 1) * 32, wn0 = (wid >> 1) * 32;
    const int g = lane >> 2, tg2 = (lane & 3) * 2;

    float acc[2][4][4];
#pragma unroll
    for (int mi = 0; mi < 2; ++mi)
#pragma unroll
        for (int nj = 0; nj < 4; ++nj)
#pragma unroll
            for (int k = 0; k < 4; ++k) acc[mi][nj][k] = 0.f;

#pragma unroll
    for (int c = 0; c < 4; ++c) {
        if (c == 0) CP_WAIT3();
        else if (c == 1) CP_WAIT2();
        else if (c == 2) CP_WAIT1();
        else CP_WAIT0();
        __syncthreads();

        unsigned short* sA = sm16 + c * ST_TOT;
        unsigned short* sB = sA + ST_A;
#pragma unroll
        for (int ks = 0; ks < 32; ks += 16) {
            unsigned a[2][4], b[4][2];
#pragma unroll
            for (int mi = 0; mi < 2; ++mi) {
                int base = (wm0 + mi * 16 + g) * GS + ks + tg2;
                a[mi][0] = lds2(sA + base);
                a[mi][1] = lds2(sA + base + 8 * GS);
                a[mi][2] = lds2(sA + base + 8);
                a[mi][3] = lds2(sA + base + 8 * GS + 8);
            }
#pragma unroll
            for (int nj = 0; nj < 4; ++nj) {
                int base = (wn0 + nj * 8 + g) * GS + ks + tg2;
                b[nj][0] = lds2(sB + base);
                b[nj][1] = lds2(sB + base + 8);
            }
#pragma unroll
            for (int mi = 0; mi < 2; ++mi)
#pragma unroll
                for (int nj = 0; nj < 4; ++nj)
                    mma16816h(acc[mi][nj], a[mi], b[nj]);
        }
    }
    __syncthreads();   // all stage reads done before epilogue overlay

    // stage P tile: sE[rtl][c*32+e], rtl = r_local*4 + t_local (8 rows x 1024)
#pragma unroll
    for (int mi = 0; mi < 2; ++mi) {
#pragma unroll
        for (int nj = 0; nj < 4; ++nj) {
            int n = wn0 + nj * 8 + tg2;
            int t_local = n >> 5, e = n & 31;
#pragma unroll
            for (int half = 0; half < 2; ++half) {
                int m = wm0 + mi * 16 + g + half * 8;
                int r_local = m >> 5, c = m & 31;
                int rtl = r_local * 4 + t_local;
                __half h0 = __float2half_rn(acc[mi][nj][half * 2 + 0]);
                __half h1 = __float2half_rn(acc[mi][nj][half * 2 + 1]);
                unsigned hp = (unsigned)__half_as_ushort(h0) |
                              ((unsigned)__half_as_ushort(h1) << 16);
                *(unsigned*)(sE + rtl * PE_STRIDE + c * 32 + e) = hp;
            }
        }
    }
    __syncthreads();

    // coalesced write: 8 complete P rows of 2KB
    const int r_base = blockIdx.y * 2, t_base = blockIdx.x * 4;
#pragma unroll
    for (int i = 0; i < 4; ++i) {
        int v = tid + 256 * i;
        int row = v >> 7, seg = v & 127;
        uint4 d = *(uint4*)(sE + row * PE_STRIDE + seg * 8);
        size_t rt = (((size_t)(r_base + (row >> 2))) << 8) + t_base + (row & 3);
        *(uint4*)((__half*)gP + rt * CE_DIM + seg * 8) = d;
    }
}

// ------------------------- kernel 3: GEMM2 -------------------------
// out[(r,t),z] = sum_ce P[rt][ce] * Wt[z][ce]. K=1024 = 32 chunks of 32,
// 4-stage ring, 2-3 chunks in flight. 3 CTAs/SM.
__global__ __launch_bounds__(256, 3) void gemm2_kernel(float* __restrict__ out) {
    extern __shared__ unsigned short sm16[];

    const int tid = threadIdx.x;
    const size_t mb = (size_t)blockIdx.x * 64;
    const int wid = tid >> 5, lane = tid & 31;
    const int wm0 = (wid & 1) * 32, wn0 = (wid >> 1) * 32;
    const int g = lane >> 2, tg2 = (lane & 3) * 2;

    auto issue = [&](int st, int kc) {
        unsigned short* sA = sm16 + st * ST_TOT;
        unsigned short* sB = sA + ST_A;
        {   // A: 64 rows (P)
            int row = tid >> 2, seg = tid & 3;
            cp16(sA + row * GS + seg * 8,
                 (const __half*)gP + (mb + row) * CE_DIM + kc + seg * 8);
        }
#pragma unroll
        for (int i = 0; i < 2; ++i) {     // B: 128 z rows (Wt)
            int idx = tid + 256 * i;
            int row = idx >> 2, seg = idx & 3;
            cp16(sB + row * GS + seg * 8,
                 (const __half*)gWt + (size_t)row * CE_DIM + kc + seg * 8);
        }
        CP_COMMIT();
    };

    float acc[2][4][4];
#pragma unroll
    for (int mi = 0; mi < 2; ++mi)
#pragma unroll
        for (int nj = 0; nj < 4; ++nj)
#pragma unroll
            for (int k = 0; k < 4; ++k) acc[mi][nj][k] = 0.f;

    issue(0, 0); issue(1, 32); issue(2, 64);

    for (int c = 0; c < 32; ++c) {
        CP_WAIT2();          // chunk c resident (<=2 groups outstanding: c+1, c+2)
        __syncthreads();     // all warps done with chunk c-1 -> its stage reusable
        if (c + 3 < 32)
            issue((c + 3) & 3, (c + 3) * 32);   // overlaps compute below

        unsigned short* sA = sm16 + (c & 3) * ST_TOT;
        unsigned short* sB = sA + ST_A;
#pragma unroll
        for (int ks = 0; ks < 32; ks += 16) {
            unsigned a[2][4], b[4][2];
#pragma unroll
            for (int mi = 0; mi < 2; ++mi) {
                int base = (wm0 + mi * 16 + g) * GS + ks + tg2;
                a[mi][0] = lds2(sA + base);
                a[mi][1] = lds2(sA + base + 8 * GS);
                a[mi][2] = lds2(sA + base + 8);
                a[mi][3] = lds2(sA + base + 8 * GS + 8);
            }
#pragma unroll
            for (int nj = 0; nj < 4; ++nj) {
                int base = (wn0 + nj * 8 + g) * GS + ks + tg2;
                b[nj][0] = lds2(sB + base);
                b[nj][1] = lds2(sB + base + 8);
            }
#pragma unroll
            for (int mi = 0; mi < 2; ++mi)
#pragma unroll
                for (int nj = 0; nj < 4; ++nj)
                    mma16816h(acc[mi][nj], a[mi], b[nj]);
        }
    }

#pragma unroll
    for (int mi = 0; mi < 2; ++mi) {
#pragma unroll
        for (int nj = 0; nj < 4; ++nj) {
            int n = wn0 + nj * 8 + tg2;
#pragma unroll
            for (int half = 0; half < 2; ++half) {
                size_t m = mb + wm0 + mi * 16 + g + half * 8;
                float2 v;
                v.x = acc[mi][nj][half * 2 + 0];
                v.y = acc[mi][nj][half * 2 + 1];
                *(float2*)(out + m * CZ_DIM + n) = v;
            }
        }
    }
}

// ------------------------- launch -------------------------
extern "C" void kernel_launch(void* const* d_in, const int* in_sizes, int n_in,
                              void* d_out, int out_size) {
    const float* msa = (const float*)d_in[0];
    const float* lw  = (const float*)d_in[1];
    const float* rw  = (const float*)d_in[2];
    const float* ow  = (const float*)d_in[3];
    float* out = (float*)d_out;

    (void)in_sizes; (void)n_in; (void)out_size;

    cudaFuncSetAttribute((const void*)proj_tc_kernel,
                         cudaFuncAttributeMaxDynamicSharedMemorySize, PROJ_SMEM);
    cudaFuncSetAttribute((const void*)gemm1_kernel,
                         cudaFuncAttributeMaxDynamicSharedMemorySize, G_SMEM);
    cudaFuncSetAttribute((const void*)gemm2_kernel,
                         cudaFuncAttributeMaxDynamicSharedMemorySize, G_SMEM);

    prep_kernel<<<(CE_DIM * CZ_DIM + 255) / 256, 256>>>(lw, rw, ow);
    proj_tc_kernel<<<R_DIM, 256, PROJ_SMEM>>>(msa);
    gemm1_kernel<<<dim3(64, 128), 256, G_SMEM>>>();
    gemm2_kernel<<<RT_DIM / 64, 256, G_SMEM>>>(out);
}